// round 1
// baseline (speedup 1.0000x reference)
#include <cuda_runtime.h>
#include <math.h>

#define B_     64
#define T_     128
#define EMB_   256
#define UNITS_ 1024
#define U3_    3072
#define M_     (B_ * T_)   // 8192

// Scratch (device globals: the sanctioned alloc-free workaround)
__device__ float g_xin[M_ * U3_];        // [B*T, 3*UNITS] input projections (+b0)
__device__ float g_h[2][B_ * UNITS_];    // ping-pong hidden state

// ---------------------------------------------------------------------------
// init hidden state buffer
// ---------------------------------------------------------------------------
__global__ void init_h_kernel(const float* __restrict__ hidden) {
    int i = blockIdx.x * blockDim.x + threadIdx.x;
    if (i < B_ * UNITS_) g_h[0][i] = hidden[i];
}

// ---------------------------------------------------------------------------
// Phase A: xin = E[x] @ W + b0
// Block tile 128(M) x 64(N), KT=32, K=256. 256 threads, thread tile 8x4.
// ---------------------------------------------------------------------------
__global__ void xin_gemm_kernel(const int* __restrict__ x,
                                const float* __restrict__ E,
                                const float* __restrict__ W,
                                const float* __restrict__ bias) {
    __shared__ float As[32][132];  // [k][m], pad to 132 (16B-aligned rows)
    __shared__ float Bs[32][68];   // [k][n], pad to 68
    __shared__ int rows[128];

    const int m0 = blockIdx.y * 128;
    const int n0 = blockIdx.x * 64;
    const int tid = threadIdx.x;         // 256
    const int tx = tid & 15;             // 16 col groups
    const int ty = tid >> 4;             // 16 row groups

    if (tid < 128) rows[tid] = x[m0 + tid];
    __syncthreads();

    float acc[8][4];
#pragma unroll
    for (int i = 0; i < 8; i++)
#pragma unroll
        for (int j = 0; j < 4; j++) acc[i][j] = 0.0f;

    for (int k0 = 0; k0 < EMB_; k0 += 32) {
        // Load A tile: 128 m x 32 k (coalesced over k), store transposed [k][m]
#pragma unroll
        for (int i = 0; i < 16; i++) {
            int idx = i * 256 + tid;
            int k = idx & 31, m = idx >> 5;
            As[k][m] = E[rows[m] * EMB_ + k0 + k];
        }
        // Load B tile: 32 k x 64 n (coalesced over n)
#pragma unroll
        for (int i = 0; i < 8; i++) {
            int idx = i * 256 + tid;
            int n = idx & 63, k = idx >> 6;
            Bs[k][n] = W[(k0 + k) * U3_ + n0 + n];
        }
        __syncthreads();

#pragma unroll
        for (int k = 0; k < 32; k++) {
            float a[8], bv[4];
#pragma unroll
            for (int i = 0; i < 8; i++) a[i] = As[k][ty * 8 + i];
#pragma unroll
            for (int j = 0; j < 4; j++) bv[j] = Bs[k][tx * 4 + j];
#pragma unroll
            for (int i = 0; i < 8; i++)
#pragma unroll
                for (int j = 0; j < 4; j++)
                    acc[i][j] = fmaf(a[i], bv[j], acc[i][j]);
        }
        __syncthreads();
    }

#pragma unroll
    for (int i = 0; i < 8; i++) {
        int m = m0 + ty * 8 + i;
#pragma unroll
        for (int j = 0; j < 4; j++) {
            int n = n0 + tx * 4 + j;
            g_xin[m * U3_ + n] = acc[i][j] + bias[n];  // + b[0]
        }
    }
}

// ---------------------------------------------------------------------------
// Phase B: one GRU step, fully fused.
// Grid: 128 blocks, each owns 8 UNITS columns (all 3 gate segments).
// 256 threads: warp w -> column c=w; lane l -> rows l and l+32.
// rec = h @ U (+b1 at epilogue), gates, h_new, output write.
// ---------------------------------------------------------------------------
__device__ __forceinline__ float sigmoidf_(float v) {
    return 1.0f / (1.0f + expf(-v));
}

__global__ void gru_step_kernel(const float* __restrict__ Umat,
                                const float* __restrict__ bias,
                                float* __restrict__ out, int t) {
    __shared__ float hs[64][65];      // [k][m], pad 65 -> conflict-free both ways
    __shared__ float Us[3][64][8];    // [seg][k][c]

    const int cur = t & 1;
    const int nxt = cur ^ 1;
    const float* __restrict__ h = g_h[cur];
    float* __restrict__ hnew = g_h[nxt];

    const int n0 = blockIdx.x * 8;
    const int tid = threadIdx.x;     // 256
    const int c = tid >> 5;          // warp id = column within tile
    const int l = tid & 31;          // lane -> rows l, l+32

    float az0 = 0.f, az1 = 0.f, ar0 = 0.f, ar1 = 0.f, ah0 = 0.f, ah1 = 0.f;

    for (int k0 = 0; k0 < UNITS_; k0 += 64) {
        // Stage h tile: 64 m x 64 k, coalesced over k, store [k][m]
#pragma unroll
        for (int i = 0; i < 16; i++) {
            int idx = i * 256 + tid;
            int k = idx & 63, m = idx >> 6;
            hs[k][m] = h[m * UNITS_ + k0 + k];
        }
        // Stage U tile: 3 seg x 64 k x 8 c
#pragma unroll
        for (int i = 0; i < 6; i++) {
            int idx = i * 256 + tid;
            int cc = idx & 7, kk = (idx >> 3) & 63, s = idx >> 9;
            Us[s][kk][cc] = Umat[(k0 + kk) * U3_ + s * UNITS_ + n0 + cc];
        }
        __syncthreads();

#pragma unroll
        for (int k = 0; k < 64; k++) {
            float h0 = hs[k][l];
            float h1 = hs[k][l + 32];
            float uz = Us[0][k][c];
            float ur = Us[1][k][c];
            float uh = Us[2][k][c];
            az0 = fmaf(h0, uz, az0); az1 = fmaf(h1, uz, az1);
            ar0 = fmaf(h0, ur, ar0); ar1 = fmaf(h1, ur, ar1);
            ah0 = fmaf(h0, uh, ah0); ah1 = fmaf(h1, uh, ah1);
        }
        __syncthreads();
    }

    const int n = n0 + c;
    const float bz = bias[U3_ + n];
    const float br = bias[U3_ + UNITS_ + n];
    const float bh = bias[U3_ + 2 * UNITS_ + n];

#pragma unroll
    for (int half = 0; half < 2; half++) {
        int m = l + half * 32;                      // batch index
        float az = half ? az1 : az0;
        float ar = half ? ar1 : ar0;
        float ah = half ? ah1 : ah0;

        const float* xrow = &g_xin[(m * T_ + t) * U3_];
        float xz = xrow[n];
        float xr = xrow[UNITS_ + n];
        float xh = xrow[2 * UNITS_ + n];

        float z = sigmoidf_(xz + az + bz);
        float r = sigmoidf_(xr + ar + br);
        float hh = tanhf(xh + r * (ah + bh));
        float hp = h[m * UNITS_ + n];
        float hn = z * hp + (1.0f - z) * hh;

        hnew[m * UNITS_ + n] = hn;
        out[(m * T_ + t) * UNITS_ + n] = hn;
        if (t == T_ - 1) {
            // final state block appended after outputs
            out[M_ * UNITS_ + m * UNITS_ + n] = hn;
        }
    }
}

// ---------------------------------------------------------------------------
// Launch: init + time-parallel GEMM + 128 sequential step kernels.
// All on the default stream (serialized, graph-capturable).
// ---------------------------------------------------------------------------
extern "C" void kernel_launch(void* const* d_in, const int* in_sizes, int n_in,
                              void* d_out, int out_size) {
    const int*   x      = (const int*)d_in[0];
    const float* hidden = (const float*)d_in[1];
    const float* E      = (const float*)d_in[2];
    const float* W      = (const float*)d_in[3];
    const float* Umat   = (const float*)d_in[4];
    const float* bias   = (const float*)d_in[5];
    float* out = (float*)d_out;

    init_h_kernel<<<(B_ * UNITS_ + 255) / 256, 256>>>(hidden);

    dim3 gridA(U3_ / 64, M_ / 128);   // (48, 64)
    xin_gemm_kernel<<<gridA, 256>>>(x, E, W, bias);

    for (int t = 0; t < T_; t++) {
        gru_step_kernel<<<UNITS_ / 8, 256>>>(Umat, bias, out, t);
    }
}